// round 14
// baseline (speedup 1.0000x reference)
#include <cuda_runtime.h>
#include <math.h>

// Problem constants (fixed by reference: H = W = 2048)
#define H_ 2048
#define W_ 2048
#define HW_ (H_ * W_)
#define LOG2W 11

// Packed direction indices (one byte per pixel), sobel -> nms. 4 MB scratch.
__device__ unsigned char g_q[HW_];

// ---------------------------------------------------------------------------
// Kernel 1: fused separable gaussian (1x5 then 5x1, zero pad 2).
// Tile 128x32 per block/channel. Identical to R12 (bit-exact, best measured).
// ---------------------------------------------------------------------------
#define TILE_X 128
#define TILE_Y 32
#define SROWS (TILE_Y + 4)
#define TX4 (TILE_X / 4)

__global__ void blur_f_k(const float* __restrict__ img, const float* __restrict__ g,
                         float* __restrict__ blurred) {
    __shared__ float4 sh4[SROWS][TX4];
    const int c = blockIdx.z;
    const int tileX0 = blockIdx.x * TILE_X;
    const int tileY0 = blockIdx.y * TILE_Y;
    const int t = threadIdx.x;          // 0..255
    const float* im = img + c * HW_;
    const float g0 = g[0], g1 = g[1], g2 = g[2], g3 = g[3], g4 = g[4];
    const float4 z4 = make_float4(0.f, 0.f, 0.f, 0.f);

    for (int u = t; u < SROWS * TX4; u += 256) {
        int r   = u >> 5;
        int cx4 = u & 31;
        int gy  = tileY0 - 2 + r;
        float4 o = z4;
        if (gy >= 0 && gy < H_) {
            const float4* row4 = (const float4*)(im + gy * W_);
            int gx = tileX0 + cx4 * 4;
            float4 L = (gx >= 4)     ? __ldg(row4 + (gx >> 2) - 1) : z4;
            float4 M =                 __ldg(row4 + (gx >> 2));
            float4 R = (gx + 4 < W_) ? __ldg(row4 + (gx >> 2) + 1) : z4;
            float v0 = L.z, v1 = L.w;
            float v2 = M.x, v3 = M.y, v4 = M.z, v5 = M.w;
            float v6 = R.x, v7 = R.y;
            o.x = fmaf(g4, v4, fmaf(g3, v3, fmaf(g2, v2, fmaf(g1, v1, __fmul_rn(g0, v0)))));
            o.y = fmaf(g4, v5, fmaf(g3, v4, fmaf(g2, v3, fmaf(g1, v2, __fmul_rn(g0, v1)))));
            o.z = fmaf(g4, v6, fmaf(g3, v5, fmaf(g2, v4, fmaf(g1, v3, __fmul_rn(g0, v2)))));
            o.w = fmaf(g4, v7, fmaf(g3, v6, fmaf(g2, v5, fmaf(g1, v4, __fmul_rn(g0, v3)))));
        }
        sh4[r][cx4] = o;
    }
    __syncthreads();

    {
        int ty0 = (t >> 5) * 4;
        int tx4 = t & 31;
        float4 r0 = sh4[ty0    ][tx4];
        float4 r1 = sh4[ty0 + 1][tx4];
        float4 r2 = sh4[ty0 + 2][tx4];
        float4 r3 = sh4[ty0 + 3][tx4];
        float4 r4 = sh4[ty0 + 4][tx4];
        float4 r5 = sh4[ty0 + 5][tx4];
        float4 r6 = sh4[ty0 + 6][tx4];
        float4 r7 = sh4[ty0 + 7][tx4];
        float* base = blurred + c * HW_ + (tileY0 + ty0) * W_ + tileX0 + tx4 * 4;

#define VBLUR(d, a0, a1, a2, a3, a4)                                                               \
        {                                                                                           \
            float4 o;                                                                               \
            o.x = fmaf(g4, a4.x, fmaf(g3, a3.x, fmaf(g2, a2.x, fmaf(g1, a1.x, __fmul_rn(g0, a0.x))))); \
            o.y = fmaf(g4, a4.y, fmaf(g3, a3.y, fmaf(g2, a2.y, fmaf(g1, a1.y, __fmul_rn(g0, a0.y))))); \
            o.z = fmaf(g4, a4.z, fmaf(g3, a3.z, fmaf(g2, a2.z, fmaf(g1, a1.z, __fmul_rn(g0, a0.z))))); \
            o.w = fmaf(g4, a4.w, fmaf(g3, a3.w, fmaf(g2, a2.w, fmaf(g1, a1.w, __fmul_rn(g0, a0.w))))); \
            *(float4*)(base + (d) * W_) = o;                                                        \
        }
        VBLUR(0, r0, r1, r2, r3, r4)
        VBLUR(1, r1, r2, r3, r4, r5)
        VBLUR(2, r2, r3, r4, r5, r6)
        VBLUR(3, r3, r4, r5, r6, r7)
#undef VBLUR
    }
}

// ---------------------------------------------------------------------------
// Shuffle edge helper: lanes cover 128 contiguous px of one row (2048/128 = 16
// warps/row, warps never straddle rows; y-predicates warp-uniform). b[x-1] is
// lane-1's v.w; b[x+4] is lane+1's v.x. Lanes 0/31 load (or zero at image edge).
// Values identical to direct loads -> bit-exact.
// ---------------------------------------------------------------------------
#define EDGE_ROW(dst, vv, ptr, lane, xl, xr)                                   \
    {                                                                          \
        dst[1] = vv.x; dst[2] = vv.y; dst[3] = vv.z; dst[4] = vv.w;            \
        float lft = __shfl_up_sync(0xffffffffu, vv.w, 1);                      \
        float rgt = __shfl_down_sync(0xffffffffu, vv.x, 1);                    \
        if (lane == 0)  lft = (xl) ? __ldg((ptr) - 1) : 0.f;                   \
        if (lane == 31) rgt = (xr) ? __ldg((ptr) + 4) : 0.f;                   \
        dst[0] = lft; dst[5] = rgt;                                            \
    }

// ---------------------------------------------------------------------------
// Kernel 2: Sobel (zero pad 1) + grad_mag + orient + early_threshold.
// 4 px/thread; edge scalars via warp shuffle. Arithmetic identical (bit-exact).
// ---------------------------------------------------------------------------
__global__ void sobel_k(const float* __restrict__ blurred,
                        const float* __restrict__ thr_p,
                        float* __restrict__ grad,
                        float* __restrict__ orient,
                        float* __restrict__ early) {
    int t4 = blockIdx.x * blockDim.x + threadIdx.x;   // float4 index
    int idx = t4 * 4;
    int x = idx & (W_ - 1);
    int y = idx >> LOG2W;
    int lane = threadIdx.x & 31;
    bool ym = (y > 0), yp = (y < H_ - 1);             // warp-uniform
    bool xl = (x > 0), xr = (x + 4 < W_);

    float mag[4] = {0.f, 0.f, 0.f, 0.f};
    float sx[4]  = {0.f, 0.f, 0.f, 0.f};
    float sy[4]  = {0.f, 0.f, 0.f, 0.f};

#pragma unroll
    for (int c = 0; c < 3; ++c) {
        const float* b = blurred + c * HW_ + y * W_ + x;
        float tp[6], md[6], bt[6];
        if (ym) {
            float4 v = __ldg((const float4*)(b - W_));
            EDGE_ROW(tp, v, b - W_, lane, xl, xr)
        } else {
            tp[0] = tp[1] = tp[2] = tp[3] = tp[4] = tp[5] = 0.f;
        }
        {
            float4 v = __ldg((const float4*)b);
            EDGE_ROW(md, v, b, lane, xl, xr)
        }
        if (yp) {
            float4 v = __ldg((const float4*)(b + W_));
            EDGE_ROW(bt, v, b + W_, lane, xl, xr)
        } else {
            bt[0] = bt[1] = bt[2] = bt[3] = bt[4] = bt[5] = 0.f;
        }
#pragma unroll
        for (int i = 0; i < 4; ++i) {
            float a00 = tp[i], a01 = tp[i + 1], a02 = tp[i + 2];
            float a10 = md[i],                  a12 = md[i + 2];
            float a20 = bt[i], a21 = bt[i + 1], a22 = bt[i + 2];
            float gx = a00;
            gx = fmaf(-1.f, a02, gx);
            gx = fmaf( 2.f, a10, gx);
            gx = fmaf(-2.f, a12, gx);
            gx = fmaf( 1.f, a20, gx);
            gx = fmaf(-1.f, a22, gx);
            float gy = a00;
            gy = fmaf( 2.f, a01, gy);
            gy = fmaf( 1.f, a02, gy);
            gy = fmaf(-1.f, a20, gy);
            gy = fmaf(-2.f, a21, gy);
            gy = fmaf(-1.f, a22, gy);

            mag[i] = __fadd_rn(mag[i], sqrtf(fmaf(gx, gx, __fmul_rn(gy, gy))));
            sx[i]  = __fadd_rn(sx[i], gx);
            sy[i]  = __fadd_rn(sy[i], gy);
        }
    }

    const float C = (float)(180.0 / 3.14159);   // NOTE: 3.14159, not pi
    float thr = __ldg(thr_p);
    float4 gm4, or4, ea4;
    float* gmA = (float*)&gm4;
    float* orA = (float*)&or4;
    float* eaA = (float*)&ea4;
    unsigned qpack = 0;
#pragma unroll
    for (int i = 0; i < 4; ++i) {
        float o  = atan2f(sy[i], sx[i]);         // libdevice __nv_atan2f (same as XLA)
        float ov = __fmul_rn(o, C);
        float tt = __fdiv_rn(__fadd_rn(ov, 180.0f), 45.0f);
        float q  = rintf(tt);                    // half-even (jnp.round)
        gmA[i] = mag[i];
        orA[i] = __fmul_rn(q, 45.0f);
        eaA[i] = (mag[i] < thr) ? 0.f : mag[i];
        qpack |= ((unsigned)(int)q) << (i * 8);  // q in [0,8]
    }
    *(float4*)(grad + idx)   = gm4;
    *(float4*)(orient + idx) = or4;
    *(float4*)(early + idx)  = ea4;
    *(unsigned*)(g_q + idx)  = qpack;
}

// ---------------------------------------------------------------------------
// Kernel 3: NMS + threshold, 4 px/thread, exact pair-max form (R12), edge
// scalars via warp shuffle:  gm > max(np, nn), pair selected by q&3:
//   0:(E,W)  1:(SE,NW)  2:(S,N)  3:(SW,NE)     (q=8 -> 0, correct)
// ---------------------------------------------------------------------------
__global__ void nms_k(const float* __restrict__ grad,
                      const float* __restrict__ thr_p,
                      float* __restrict__ thin,
                      float* __restrict__ thresh) {
    int t4 = blockIdx.x * blockDim.x + threadIdx.x;
    int idx = t4 * 4;
    int x = idx & (W_ - 1);
    int y = idx >> LOG2W;
    int lane = threadIdx.x & 31;
    bool ym = (y > 0), yp = (y < H_ - 1);             // warp-uniform
    bool xl = (x > 0), xr = (x + 4 < W_);

    const float* b = grad + y * W_ + x;
    float tp[6], md[6], bt[6];
    if (ym) {
        float4 v = __ldg((const float4*)(b - W_));
        EDGE_ROW(tp, v, b - W_, lane, xl, xr)
    } else {
        tp[0] = tp[1] = tp[2] = tp[3] = tp[4] = tp[5] = 0.f;
    }
    {
        float4 v = __ldg((const float4*)b);
        EDGE_ROW(md, v, b, lane, xl, xr)
    }
    if (yp) {
        float4 v = __ldg((const float4*)(b + W_));
        EDGE_ROW(bt, v, b + W_, lane, xl, xr)
    } else {
        bt[0] = bt[1] = bt[2] = bt[3] = bt[4] = bt[5] = 0.f;
    }

    unsigned qpack = *(const unsigned*)(g_q + idx);
    float thr = __ldg(thr_p);

    float4 th4, ts4;
    float* thA = (float*)&th4;
    float* tsA = (float*)&ts4;
#pragma unroll
    for (int i = 0; i < 4; ++i) {
        float gm = md[i + 1];
        int p = (int)((qpack >> (i * 8)) & 3u);   // pair index

        float pm0 = fmaxf(md[i + 2], md[i]);       // E , W
        float pm1 = fmaxf(bt[i + 2], tp[i]);       // SE, NW
        float pm2 = fmaxf(bt[i + 1], tp[i + 1]);   // S , N
        float pm3 = fmaxf(bt[i],     tp[i + 2]);   // SW, NE
        float pm = (p < 2) ? ((p == 0) ? pm0 : pm1)
                           : ((p == 2) ? pm2 : pm3);

        float tv = (gm > pm) ? gm : 0.f;
        thA[i] = tv;
        tsA[i] = (tv < thr) ? 0.f : tv;
    }
    *(float4*)(thin + idx)   = th4;
    *(float4*)(thresh + idx) = ts4;
}

// ---------------------------------------------------------------------------
// Launch
// Inputs: img[3HW], threshold[1], gauss_h[5], gauss_v[5], sobel_h[9],
//         sobel_v[9], dir_w[72]
// Output: [0,3HW) blurred | [3HW,4HW) grad | [4HW,5HW) orient |
//         [5HW,6HW) thin | [6HW,7HW) thresholded | [7HW,8HW) early
// ---------------------------------------------------------------------------
extern "C" void kernel_launch(void* const* d_in, const int* in_sizes, int n_in,
                              void* d_out, int out_size) {
    const float* img   = (const float*)d_in[0];
    const float* thr   = (const float*)d_in[1];
    const float* gauss = (const float*)d_in[2];

    float* out      = (float*)d_out;
    float* blurred  = out;
    float* grad     = out + 3 * HW_;
    float* orient   = out + 4 * HW_;
    float* thin     = out + 5 * HW_;
    float* thresh   = out + 6 * HW_;
    float* early    = out + 7 * HW_;

    dim3 bgrid(W_ / TILE_X, H_ / TILE_Y, 3);   // 16 x 64 x 3
    blur_f_k<<<bgrid, 256>>>(img, gauss, blurred);

    int blocks4 = (HW_ / 4 + 255) / 256;        // 4096
    sobel_k<<<blocks4, 256>>>(blurred, thr, grad, orient, early);
    nms_k<<<blocks4, 256>>>(grad, thr, thin, thresh);
}

// round 15
// speedup vs baseline: 1.1508x; 1.1508x over previous
#include <cuda_runtime.h>
#include <math.h>

// Problem constants (fixed by reference: H = W = 2048)
#define H_ 2048
#define W_ 2048
#define HW_ (H_ * W_)
#define LOG2W 11

// Packed direction indices (one byte per pixel), sobel -> nms. 4 MB scratch.
__device__ unsigned char g_q[HW_];

// ---------------------------------------------------------------------------
// Kernel 1: fused separable gaussian (1x5 then 5x1, zero pad 2).
// Tile 128x32 per block/channel. Identical to R12 (bit-exact, best measured).
// ---------------------------------------------------------------------------
#define TILE_X 128
#define TILE_Y 32
#define SROWS (TILE_Y + 4)
#define TX4 (TILE_X / 4)

__global__ void blur_f_k(const float* __restrict__ img, const float* __restrict__ g,
                         float* __restrict__ blurred) {
    __shared__ float4 sh4[SROWS][TX4];
    const int c = blockIdx.z;
    const int tileX0 = blockIdx.x * TILE_X;
    const int tileY0 = blockIdx.y * TILE_Y;
    const int t = threadIdx.x;          // 0..255
    const float* im = img + c * HW_;
    const float g0 = g[0], g1 = g[1], g2 = g[2], g3 = g[3], g4 = g[4];
    const float4 z4 = make_float4(0.f, 0.f, 0.f, 0.f);

    for (int u = t; u < SROWS * TX4; u += 256) {
        int r   = u >> 5;
        int cx4 = u & 31;
        int gy  = tileY0 - 2 + r;
        float4 o = z4;
        if (gy >= 0 && gy < H_) {
            const float4* row4 = (const float4*)(im + gy * W_);
            int gx = tileX0 + cx4 * 4;
            float4 L = (gx >= 4)     ? __ldg(row4 + (gx >> 2) - 1) : z4;
            float4 M =                 __ldg(row4 + (gx >> 2));
            float4 R = (gx + 4 < W_) ? __ldg(row4 + (gx >> 2) + 1) : z4;
            float v0 = L.z, v1 = L.w;
            float v2 = M.x, v3 = M.y, v4 = M.z, v5 = M.w;
            float v6 = R.x, v7 = R.y;
            o.x = fmaf(g4, v4, fmaf(g3, v3, fmaf(g2, v2, fmaf(g1, v1, __fmul_rn(g0, v0)))));
            o.y = fmaf(g4, v5, fmaf(g3, v4, fmaf(g2, v3, fmaf(g1, v2, __fmul_rn(g0, v1)))));
            o.z = fmaf(g4, v6, fmaf(g3, v5, fmaf(g2, v4, fmaf(g1, v3, __fmul_rn(g0, v2)))));
            o.w = fmaf(g4, v7, fmaf(g3, v6, fmaf(g2, v5, fmaf(g1, v4, __fmul_rn(g0, v3)))));
        }
        sh4[r][cx4] = o;
    }
    __syncthreads();

    {
        int ty0 = (t >> 5) * 4;
        int tx4 = t & 31;
        float4 r0 = sh4[ty0    ][tx4];
        float4 r1 = sh4[ty0 + 1][tx4];
        float4 r2 = sh4[ty0 + 2][tx4];
        float4 r3 = sh4[ty0 + 3][tx4];
        float4 r4 = sh4[ty0 + 4][tx4];
        float4 r5 = sh4[ty0 + 5][tx4];
        float4 r6 = sh4[ty0 + 6][tx4];
        float4 r7 = sh4[ty0 + 7][tx4];
        float* base = blurred + c * HW_ + (tileY0 + ty0) * W_ + tileX0 + tx4 * 4;

#define VBLUR(d, a0, a1, a2, a3, a4)                                                               \
        {                                                                                           \
            float4 o;                                                                               \
            o.x = fmaf(g4, a4.x, fmaf(g3, a3.x, fmaf(g2, a2.x, fmaf(g1, a1.x, __fmul_rn(g0, a0.x))))); \
            o.y = fmaf(g4, a4.y, fmaf(g3, a3.y, fmaf(g2, a2.y, fmaf(g1, a1.y, __fmul_rn(g0, a0.y))))); \
            o.z = fmaf(g4, a4.z, fmaf(g3, a3.z, fmaf(g2, a2.z, fmaf(g1, a1.z, __fmul_rn(g0, a0.z))))); \
            o.w = fmaf(g4, a4.w, fmaf(g3, a3.w, fmaf(g2, a2.w, fmaf(g1, a1.w, __fmul_rn(g0, a0.w))))); \
            *(float4*)(base + (d) * W_) = o;                                                        \
        }
        VBLUR(0, r0, r1, r2, r3, r4)
        VBLUR(1, r1, r2, r3, r4, r5)
        VBLUR(2, r2, r3, r4, r5, r6)
        VBLUR(3, r3, r4, r5, r6, r7)
#undef VBLUR
    }
}

// ---------------------------------------------------------------------------
// Kernel 2: Sobel (zero pad 1) + grad_mag + orient + early_threshold.
// 4 px/thread, plus packed q-byte store. Identical to R9/R12 (bit-exact).
// ---------------------------------------------------------------------------
__global__ void sobel_k(const float* __restrict__ blurred,
                        const float* __restrict__ thr_p,
                        float* __restrict__ grad,
                        float* __restrict__ orient,
                        float* __restrict__ early) {
    int t4 = blockIdx.x * blockDim.x + threadIdx.x;   // float4 index
    int idx = t4 * 4;
    int x = idx & (W_ - 1);
    int y = idx >> LOG2W;
    bool ym = (y > 0), yp = (y < H_ - 1);
    bool xl = (x > 0), xr = (x + 4 < W_);

    float mag[4] = {0.f, 0.f, 0.f, 0.f};
    float sx[4]  = {0.f, 0.f, 0.f, 0.f};
    float sy[4]  = {0.f, 0.f, 0.f, 0.f};

#pragma unroll
    for (int c = 0; c < 3; ++c) {
        const float* b = blurred + c * HW_ + y * W_ + x;
        float tp[6], md[6], bt[6];
        if (ym) {
            float4 v = __ldg((const float4*)(b - W_));
            tp[1] = v.x; tp[2] = v.y; tp[3] = v.z; tp[4] = v.w;
            tp[0] = xl ? __ldg(b - W_ - 1) : 0.f;
            tp[5] = xr ? __ldg(b - W_ + 4) : 0.f;
        } else {
            tp[0] = tp[1] = tp[2] = tp[3] = tp[4] = tp[5] = 0.f;
        }
        {
            float4 v = __ldg((const float4*)b);
            md[1] = v.x; md[2] = v.y; md[3] = v.z; md[4] = v.w;
            md[0] = xl ? __ldg(b - 1) : 0.f;
            md[5] = xr ? __ldg(b + 4) : 0.f;
        }
        if (yp) {
            float4 v = __ldg((const float4*)(b + W_));
            bt[1] = v.x; bt[2] = v.y; bt[3] = v.z; bt[4] = v.w;
            bt[0] = xl ? __ldg(b + W_ - 1) : 0.f;
            bt[5] = xr ? __ldg(b + W_ + 4) : 0.f;
        } else {
            bt[0] = bt[1] = bt[2] = bt[3] = bt[4] = bt[5] = 0.f;
        }
#pragma unroll
        for (int i = 0; i < 4; ++i) {
            float a00 = tp[i], a01 = tp[i + 1], a02 = tp[i + 2];
            float a10 = md[i],                  a12 = md[i + 2];
            float a20 = bt[i], a21 = bt[i + 1], a22 = bt[i + 2];
            float gx = a00;
            gx = fmaf(-1.f, a02, gx);
            gx = fmaf( 2.f, a10, gx);
            gx = fmaf(-2.f, a12, gx);
            gx = fmaf( 1.f, a20, gx);
            gx = fmaf(-1.f, a22, gx);
            float gy = a00;
            gy = fmaf( 2.f, a01, gy);
            gy = fmaf( 1.f, a02, gy);
            gy = fmaf(-1.f, a20, gy);
            gy = fmaf(-2.f, a21, gy);
            gy = fmaf(-1.f, a22, gy);

            mag[i] = __fadd_rn(mag[i], sqrtf(fmaf(gx, gx, __fmul_rn(gy, gy))));
            sx[i]  = __fadd_rn(sx[i], gx);
            sy[i]  = __fadd_rn(sy[i], gy);
        }
    }

    const float C = (float)(180.0 / 3.14159);   // NOTE: 3.14159, not pi
    float thr = __ldg(thr_p);
    float4 gm4, or4, ea4;
    float* gmA = (float*)&gm4;
    float* orA = (float*)&or4;
    float* eaA = (float*)&ea4;
    unsigned qpack = 0;
#pragma unroll
    for (int i = 0; i < 4; ++i) {
        float o  = atan2f(sy[i], sx[i]);         // libdevice __nv_atan2f (same as XLA)
        float ov = __fmul_rn(o, C);
        float tt = __fdiv_rn(__fadd_rn(ov, 180.0f), 45.0f);
        float q  = rintf(tt);                    // half-even (jnp.round)
        gmA[i] = mag[i];
        orA[i] = __fmul_rn(q, 45.0f);
        eaA[i] = (mag[i] < thr) ? 0.f : mag[i];
        qpack |= ((unsigned)(int)q) << (i * 8);  // q in [0,8]
    }
    *(float4*)(grad + idx)   = gm4;
    *(float4*)(orient + idx) = or4;
    *(float4*)(early + idx)  = ea4;
    *(unsigned*)(g_q + idx)  = qpack;
}

// ---------------------------------------------------------------------------
// Kernel 3: NMS + threshold, 4 px/thread, exact pair-max form. Identical to
// R12 (bit-exact):
//   min(rn(gm-np), rn(gm-nn)) > 0  <=>  gm > np && gm > nn  <=>  gm > max(np,nn)
// (f32 subtraction is sign-exact). Neighbors are point-symmetric (kn = kp+4),
// so max(np,nn) is one of 4 pair-maxes selected by q&3:
//   0:(E,W)  1:(SE,NW)  2:(S,N)  3:(SW,NE)     (q=8 -> 0, correct)
// Zero-filled borders == reference zero padding.
// ---------------------------------------------------------------------------
__global__ void nms_k(const float* __restrict__ grad,
                      const float* __restrict__ thr_p,
                      float* __restrict__ thin,
                      float* __restrict__ thresh) {
    int t4 = blockIdx.x * blockDim.x + threadIdx.x;
    int idx = t4 * 4;
    int x = idx & (W_ - 1);
    int y = idx >> LOG2W;
    bool ym = (y > 0), yp = (y < H_ - 1);
    bool xl = (x > 0), xr = (x + 4 < W_);

    const float* b = grad + y * W_ + x;
    float tp[6], md[6], bt[6];
    if (ym) {
        float4 v = __ldg((const float4*)(b - W_));
        tp[1] = v.x; tp[2] = v.y; tp[3] = v.z; tp[4] = v.w;
        tp[0] = xl ? __ldg(b - W_ - 1) : 0.f;
        tp[5] = xr ? __ldg(b - W_ + 4) : 0.f;
    } else {
        tp[0] = tp[1] = tp[2] = tp[3] = tp[4] = tp[5] = 0.f;
    }
    {
        float4 v = __ldg((const float4*)b);
        md[1] = v.x; md[2] = v.y; md[3] = v.z; md[4] = v.w;
        md[0] = xl ? __ldg(b - 1) : 0.f;
        md[5] = xr ? __ldg(b + 4) : 0.f;
    }
    if (yp) {
        float4 v = __ldg((const float4*)(b + W_));
        bt[1] = v.x; bt[2] = v.y; bt[3] = v.z; bt[4] = v.w;
        bt[0] = xl ? __ldg(b + W_ - 1) : 0.f;
        bt[5] = xr ? __ldg(b + W_ + 4) : 0.f;
    } else {
        bt[0] = bt[1] = bt[2] = bt[3] = bt[4] = bt[5] = 0.f;
    }

    unsigned qpack = *(const unsigned*)(g_q + idx);
    float thr = __ldg(thr_p);

    float4 th4, ts4;
    float* thA = (float*)&th4;
    float* tsA = (float*)&ts4;
#pragma unroll
    for (int i = 0; i < 4; ++i) {
        float gm = md[i + 1];
        int p = (int)((qpack >> (i * 8)) & 3u);   // pair index

        float pm0 = fmaxf(md[i + 2], md[i]);       // E , W
        float pm1 = fmaxf(bt[i + 2], tp[i]);       // SE, NW
        float pm2 = fmaxf(bt[i + 1], tp[i + 1]);   // S , N
        float pm3 = fmaxf(bt[i],     tp[i + 2]);   // SW, NE
        float pm = (p < 2) ? ((p == 0) ? pm0 : pm1)
                           : ((p == 2) ? pm2 : pm3);

        float tv = (gm > pm) ? gm : 0.f;
        thA[i] = tv;
        tsA[i] = (tv < thr) ? 0.f : tv;
    }
    *(float4*)(thin + idx)   = th4;
    *(float4*)(thresh + idx) = ts4;
}

// ---------------------------------------------------------------------------
// Launch
// Inputs: img[3HW], threshold[1], gauss_h[5], gauss_v[5], sobel_h[9],
//         sobel_v[9], dir_w[72]
// Output: [0,3HW) blurred | [3HW,4HW) grad | [4HW,5HW) orient |
//         [5HW,6HW) thin | [6HW,7HW) thresholded | [7HW,8HW) early
// ---------------------------------------------------------------------------
extern "C" void kernel_launch(void* const* d_in, const int* in_sizes, int n_in,
                              void* d_out, int out_size) {
    const float* img   = (const float*)d_in[0];
    const float* thr   = (const float*)d_in[1];
    const float* gauss = (const float*)d_in[2];

    float* out      = (float*)d_out;
    float* blurred  = out;
    float* grad     = out + 3 * HW_;
    float* orient   = out + 4 * HW_;
    float* thin     = out + 5 * HW_;
    float* thresh   = out + 6 * HW_;
    float* early    = out + 7 * HW_;

    dim3 bgrid(W_ / TILE_X, H_ / TILE_Y, 3);   // 16 x 64 x 3
    blur_f_k<<<bgrid, 256>>>(img, gauss, blurred);

    int blocks4 = (HW_ / 4 + 255) / 256;        // 4096
    sobel_k<<<blocks4, 256>>>(blurred, thr, grad, orient, early);
    nms_k<<<blocks4, 256>>>(grad, thr, thin, thresh);
}

// round 16
// speedup vs baseline: 1.1575x; 1.0059x over previous
#include <cuda_runtime.h>
#include <math.h>

// Problem constants (fixed by reference: H = W = 2048)
#define H_ 2048
#define W_ 2048
#define HW_ (H_ * W_)
#define LOG2W 11

// Packed direction indices (one byte per pixel), sobel -> nms. 4 MB scratch.
__device__ unsigned char g_q[HW_];

// ---------------------------------------------------------------------------
// Kernel 1: fused separable gaussian (1x5 then 5x1, zero pad 2).
// Tile 128x32 per block/channel. Identical to R12/R15 (bit-exact, best).
// ---------------------------------------------------------------------------
#define TILE_X 128
#define TILE_Y 32
#define SROWS (TILE_Y + 4)
#define TX4 (TILE_X / 4)

__global__ void blur_f_k(const float* __restrict__ img, const float* __restrict__ g,
                         float* __restrict__ blurred) {
    __shared__ float4 sh4[SROWS][TX4];
    const int c = blockIdx.z;
    const int tileX0 = blockIdx.x * TILE_X;
    const int tileY0 = blockIdx.y * TILE_Y;
    const int t = threadIdx.x;          // 0..255
    const float* im = img + c * HW_;
    const float g0 = g[0], g1 = g[1], g2 = g[2], g3 = g[3], g4 = g[4];
    const float4 z4 = make_float4(0.f, 0.f, 0.f, 0.f);

    for (int u = t; u < SROWS * TX4; u += 256) {
        int r   = u >> 5;
        int cx4 = u & 31;
        int gy  = tileY0 - 2 + r;
        float4 o = z4;
        if (gy >= 0 && gy < H_) {
            const float4* row4 = (const float4*)(im + gy * W_);
            int gx = tileX0 + cx4 * 4;
            float4 L = (gx >= 4)     ? __ldg(row4 + (gx >> 2) - 1) : z4;
            float4 M =                 __ldg(row4 + (gx >> 2));
            float4 R = (gx + 4 < W_) ? __ldg(row4 + (gx >> 2) + 1) : z4;
            float v0 = L.z, v1 = L.w;
            float v2 = M.x, v3 = M.y, v4 = M.z, v5 = M.w;
            float v6 = R.x, v7 = R.y;
            o.x = fmaf(g4, v4, fmaf(g3, v3, fmaf(g2, v2, fmaf(g1, v1, __fmul_rn(g0, v0)))));
            o.y = fmaf(g4, v5, fmaf(g3, v4, fmaf(g2, v3, fmaf(g1, v2, __fmul_rn(g0, v1)))));
            o.z = fmaf(g4, v6, fmaf(g3, v5, fmaf(g2, v4, fmaf(g1, v3, __fmul_rn(g0, v2)))));
            o.w = fmaf(g4, v7, fmaf(g3, v6, fmaf(g2, v5, fmaf(g1, v4, __fmul_rn(g0, v3)))));
        }
        sh4[r][cx4] = o;
    }
    __syncthreads();

    {
        int ty0 = (t >> 5) * 4;
        int tx4 = t & 31;
        float4 r0 = sh4[ty0    ][tx4];
        float4 r1 = sh4[ty0 + 1][tx4];
        float4 r2 = sh4[ty0 + 2][tx4];
        float4 r3 = sh4[ty0 + 3][tx4];
        float4 r4 = sh4[ty0 + 4][tx4];
        float4 r5 = sh4[ty0 + 5][tx4];
        float4 r6 = sh4[ty0 + 6][tx4];
        float4 r7 = sh4[ty0 + 7][tx4];
        float* base = blurred + c * HW_ + (tileY0 + ty0) * W_ + tileX0 + tx4 * 4;

#define VBLUR(d, a0, a1, a2, a3, a4)                                                               \
        {                                                                                           \
            float4 o;                                                                               \
            o.x = fmaf(g4, a4.x, fmaf(g3, a3.x, fmaf(g2, a2.x, fmaf(g1, a1.x, __fmul_rn(g0, a0.x))))); \
            o.y = fmaf(g4, a4.y, fmaf(g3, a3.y, fmaf(g2, a2.y, fmaf(g1, a1.y, __fmul_rn(g0, a0.y))))); \
            o.z = fmaf(g4, a4.z, fmaf(g3, a3.z, fmaf(g2, a2.z, fmaf(g1, a1.z, __fmul_rn(g0, a0.z))))); \
            o.w = fmaf(g4, a4.w, fmaf(g3, a3.w, fmaf(g2, a2.w, fmaf(g1, a1.w, __fmul_rn(g0, a0.w))))); \
            *(float4*)(base + (d) * W_) = o;                                                        \
        }
        VBLUR(0, r0, r1, r2, r3, r4)
        VBLUR(1, r1, r2, r3, r4, r5)
        VBLUR(2, r2, r3, r4, r5, r6)
        VBLUR(3, r3, r4, r5, r6, r7)
#undef VBLUR
    }
}

// ---------------------------------------------------------------------------
// Kernel 2: Sobel (zero pad 1) + grad_mag + orient + early_threshold.
// 4 px/thread. Conv chains identical to R12/R15 (bit-exact).
// Orientation: certified sector classification; atan2f pipeline (the exact
// R15 code) only for pixels within a 3e-5 rel margin of a bin boundary.
//
// Reference bin: q = rintf((atan2f(sy,sx)*C + 180)/45), C = (float)(180/3.14159).
// Boundaries at theta = (45k-157.5)/C. Because C != 180/pi, boundary |tan|
// differs by quadrant sign of sx:
//   sx>0: T1 = tan(22.5*3.14159/180)  = 0.4142131738
//         T2 = tan(67.5*3.14159/180)  = 2.4142067672
//   sx<0: T1 = tan(pi - 157.5*3.14159/180) = 0.4142162824
//         T2 = tan(pi - 112.5*3.14159/180) = 2.4142248873
// Pipeline bin uncertainty <= ~2.1e-6 rad (atan2f 2ulp + mul/add/div
// roundings) << margin 1.1e-5 rad  ->  fast path provably matches.
// ---------------------------------------------------------------------------
__global__ void sobel_k(const float* __restrict__ blurred,
                        const float* __restrict__ thr_p,
                        float* __restrict__ grad,
                        float* __restrict__ orient,
                        float* __restrict__ early) {
    int t4 = blockIdx.x * blockDim.x + threadIdx.x;   // float4 index
    int idx = t4 * 4;
    int x = idx & (W_ - 1);
    int y = idx >> LOG2W;
    bool ym = (y > 0), yp = (y < H_ - 1);
    bool xl = (x > 0), xr = (x + 4 < W_);

    float mag[4] = {0.f, 0.f, 0.f, 0.f};
    float sx[4]  = {0.f, 0.f, 0.f, 0.f};
    float sy[4]  = {0.f, 0.f, 0.f, 0.f};

#pragma unroll
    for (int c = 0; c < 3; ++c) {
        const float* b = blurred + c * HW_ + y * W_ + x;
        float tp[6], md[6], bt[6];
        if (ym) {
            float4 v = __ldg((const float4*)(b - W_));
            tp[1] = v.x; tp[2] = v.y; tp[3] = v.z; tp[4] = v.w;
            tp[0] = xl ? __ldg(b - W_ - 1) : 0.f;
            tp[5] = xr ? __ldg(b - W_ + 4) : 0.f;
        } else {
            tp[0] = tp[1] = tp[2] = tp[3] = tp[4] = tp[5] = 0.f;
        }
        {
            float4 v = __ldg((const float4*)b);
            md[1] = v.x; md[2] = v.y; md[3] = v.z; md[4] = v.w;
            md[0] = xl ? __ldg(b - 1) : 0.f;
            md[5] = xr ? __ldg(b + 4) : 0.f;
        }
        if (yp) {
            float4 v = __ldg((const float4*)(b + W_));
            bt[1] = v.x; bt[2] = v.y; bt[3] = v.z; bt[4] = v.w;
            bt[0] = xl ? __ldg(b + W_ - 1) : 0.f;
            bt[5] = xr ? __ldg(b + W_ + 4) : 0.f;
        } else {
            bt[0] = bt[1] = bt[2] = bt[3] = bt[4] = bt[5] = 0.f;
        }
#pragma unroll
        for (int i = 0; i < 4; ++i) {
            float a00 = tp[i], a01 = tp[i + 1], a02 = tp[i + 2];
            float a10 = md[i],                  a12 = md[i + 2];
            float a20 = bt[i], a21 = bt[i + 1], a22 = bt[i + 2];
            float gx = a00;
            gx = fmaf(-1.f, a02, gx);
            gx = fmaf( 2.f, a10, gx);
            gx = fmaf(-2.f, a12, gx);
            gx = fmaf( 1.f, a20, gx);
            gx = fmaf(-1.f, a22, gx);
            float gy = a00;
            gy = fmaf( 2.f, a01, gy);
            gy = fmaf( 1.f, a02, gy);
            gy = fmaf(-1.f, a20, gy);
            gy = fmaf(-2.f, a21, gy);
            gy = fmaf(-1.f, a22, gy);

            mag[i] = __fadd_rn(mag[i], sqrtf(fmaf(gx, gx, __fmul_rn(gy, gy))));
            sx[i]  = __fadd_rn(sx[i], gx);
            sy[i]  = __fadd_rn(sy[i], gy);
        }
    }

    const float C = (float)(180.0 / 3.14159);   // NOTE: 3.14159, not pi
    const float ML = 1.0f - 3e-5f, MH = 1.0f + 3e-5f;
    float thr = __ldg(thr_p);
    float4 gm4, or4, ea4;
    float* gmA = (float*)&gm4;
    float* orA = (float*)&or4;
    float* eaA = (float*)&ea4;
    unsigned qpack = 0;
#pragma unroll
    for (int i = 0; i < 4; ++i) {
        float sxv = sx[i], syv = sy[i];
        float ax = fabsf(sxv), ay = fabsf(syv);
        bool neg = (sxv < 0.f);
        float T1 = neg ? 0.4142162824f : 0.4142131738f;
        float T2 = neg ? 2.4142248873f : 2.4142067672f;

        int qi = 0;
        bool slow = false;
        if (ay < T1 * ML * ax) {
            // horizontal band: theta near 0 (q=4) or near +-180 (q=8 / q=0)
            qi = !neg ? 4 : (signbit(syv) ? 0 : 8);
        } else if (ay > T2 * MH * ax) {
            // vertical band (ay > 0 here, so syv != +-0)
            qi = (syv < 0.f) ? 2 : 6;
        } else if (ay > T1 * MH * ax && ay < T2 * ML * ax) {
            // diagonal band (syv != 0 here: ax>0 else caught by vertical)
            qi = (syv > 0.f) ? (neg ? 7 : 5) : (neg ? 1 : 3);
        } else {
            slow = true;                 // ambiguous (incl. sx=sy=0)
        }
        if (slow) {
            // exact R15 pipeline (bit-identical fallback)
            float o  = atan2f(syv, sxv);             // libdevice __nv_atan2f
            float ov = __fmul_rn(o, C);
            float tt = __fdiv_rn(__fadd_rn(ov, 180.0f), 45.0f);
            qi = (int)rintf(tt);                     // half-even (jnp.round)
        }

        gmA[i] = mag[i];
        orA[i] = __fmul_rn((float)qi, 45.0f);
        eaA[i] = (mag[i] < thr) ? 0.f : mag[i];
        qpack |= ((unsigned)qi) << (i * 8);          // q in [0,8]
    }
    *(float4*)(grad + idx)   = gm4;
    *(float4*)(orient + idx) = or4;
    *(float4*)(early + idx)  = ea4;
    *(unsigned*)(g_q + idx)  = qpack;
}

// ---------------------------------------------------------------------------
// Kernel 3: NMS + threshold, 4 px/thread, exact pair-max form. Identical to
// R12/R15 (bit-exact):  gm > max(np, nn), pair selected by q&3:
//   0:(E,W)  1:(SE,NW)  2:(S,N)  3:(SW,NE)     (q=8 -> 0, correct)
// ---------------------------------------------------------------------------
__global__ void nms_k(const float* __restrict__ grad,
                      const float* __restrict__ thr_p,
                      float* __restrict__ thin,
                      float* __restrict__ thresh) {
    int t4 = blockIdx.x * blockDim.x + threadIdx.x;
    int idx = t4 * 4;
    int x = idx & (W_ - 1);
    int y = idx >> LOG2W;
    bool ym = (y > 0), yp = (y < H_ - 1);
    bool xl = (x > 0), xr = (x + 4 < W_);

    const float* b = grad + y * W_ + x;
    float tp[6], md[6], bt[6];
    if (ym) {
        float4 v = __ldg((const float4*)(b - W_));
        tp[1] = v.x; tp[2] = v.y; tp[3] = v.z; tp[4] = v.w;
        tp[0] = xl ? __ldg(b - W_ - 1) : 0.f;
        tp[5] = xr ? __ldg(b - W_ + 4) : 0.f;
    } else {
        tp[0] = tp[1] = tp[2] = tp[3] = tp[4] = tp[5] = 0.f;
    }
    {
        float4 v = __ldg((const float4*)b);
        md[1] = v.x; md[2] = v.y; md[3] = v.z; md[4] = v.w;
        md[0] = xl ? __ldg(b - 1) : 0.f;
        md[5] = xr ? __ldg(b + 4) : 0.f;
    }
    if (yp) {
        float4 v = __ldg((const float4*)(b + W_));
        bt[1] = v.x; bt[2] = v.y; bt[3] = v.z; bt[4] = v.w;
        bt[0] = xl ? __ldg(b + W_ - 1) : 0.f;
        bt[5] = xr ? __ldg(b + W_ + 4) : 0.f;
    } else {
        bt[0] = bt[1] = bt[2] = bt[3] = bt[4] = bt[5] = 0.f;
    }

    unsigned qpack = *(const unsigned*)(g_q + idx);
    float thr = __ldg(thr_p);

    float4 th4, ts4;
    float* thA = (float*)&th4;
    float* tsA = (float*)&ts4;
#pragma unroll
    for (int i = 0; i < 4; ++i) {
        float gm = md[i + 1];
        int p = (int)((qpack >> (i * 8)) & 3u);   // pair index

        float pm0 = fmaxf(md[i + 2], md[i]);       // E , W
        float pm1 = fmaxf(bt[i + 2], tp[i]);       // SE, NW
        float pm2 = fmaxf(bt[i + 1], tp[i + 1]);   // S , N
        float pm3 = fmaxf(bt[i],     tp[i + 2]);   // SW, NE
        float pm = (p < 2) ? ((p == 0) ? pm0 : pm1)
                           : ((p == 2) ? pm2 : pm3);

        float tv = (gm > pm) ? gm : 0.f;
        thA[i] = tv;
        tsA[i] = (tv < thr) ? 0.f : tv;
    }
    *(float4*)(thin + idx)   = th4;
    *(float4*)(thresh + idx) = ts4;
}

// ---------------------------------------------------------------------------
// Launch
// Inputs: img[3HW], threshold[1], gauss_h[5], gauss_v[5], sobel_h[9],
//         sobel_v[9], dir_w[72]
// Output: [0,3HW) blurred | [3HW,4HW) grad | [4HW,5HW) orient |
//         [5HW,6HW) thin | [6HW,7HW) thresholded | [7HW,8HW) early
// ---------------------------------------------------------------------------
extern "C" void kernel_launch(void* const* d_in, const int* in_sizes, int n_in,
                              void* d_out, int out_size) {
    const float* img   = (const float*)d_in[0];
    const float* thr   = (const float*)d_in[1];
    const float* gauss = (const float*)d_in[2];

    float* out      = (float*)d_out;
    float* blurred  = out;
    float* grad     = out + 3 * HW_;
    float* orient   = out + 4 * HW_;
    float* thin     = out + 5 * HW_;
    float* thresh   = out + 6 * HW_;
    float* early    = out + 7 * HW_;

    dim3 bgrid(W_ / TILE_X, H_ / TILE_Y, 3);   // 16 x 64 x 3
    blur_f_k<<<bgrid, 256>>>(img, gauss, blurred);

    int blocks4 = (HW_ / 4 + 255) / 256;        // 4096
    sobel_k<<<blocks4, 256>>>(blurred, thr, grad, orient, early);
    nms_k<<<blocks4, 256>>>(grad, thr, thin, thresh);
}